// round 4
// baseline (speedup 1.0000x reference)
#include <cuda_runtime.h>
#include <cstddef>

// GATNE-T fully fused single kernel.
// Inputs (metadata order):
//  0 targets   int32  [B]
//  1 types     int32  [B]
//  2 neighbors int32  [B,T,S]
//  3 base_node_embeddings float [V,E]
//  4 node_type_embeddings float [V,T,D]
//  5 trans_weights    float [T,D,E]
//  6 trans_weights_s1 float [T,D,A]
//  7 trans_weights_s2 float [T,A,1]
// Output: float [B,E]
//
// One CTA = 128 threads = 4 warps, processes G1 batch elements sequentially.
// Per b:
//   gather:    warp t, lane d  -> sh_agg[t][d]   (random 128B DRAM gathers)
//   attention: the warp whose id == types[b] owns the register-cached
//              W1[type] column / w2[type] and computes scores+softmax+natt
//   projection: warp w computes outputs e in [32w, 32w+32) reading
//              trans_weights via __ldg (64KB table -> L1-resident)
//   l2 norm:   warp partials in smem, combined by all.

namespace {
constexpr int T = 4;
constexpr int S = 10;
constexpr int D = 32;
constexpr int E = 128;
constexpr int A = 32;
constexpr int G1 = 16;    // batch elements per CTA
}

__global__ __launch_bounds__(128) void gatne_fused(
    const int*   __restrict__ targets,
    const int*   __restrict__ types,
    const int*   __restrict__ neighbors,  // [B,T,S]
    const float* __restrict__ base_emb,   // [V,E]
    const float* __restrict__ nte,        // [V,T,D]
    const float* __restrict__ tw,         // [T,D,E]
    const float* __restrict__ tw1,        // [T,D,A]
    const float* __restrict__ tw2,        // [T,A]
    float*       __restrict__ out,        // [B,E]
    int B)
{
    const int warp = threadIdx.x >> 5;
    const int lane = threadIdx.x & 31;

    __shared__ float sh_agg[T][D];
    __shared__ float sh_natt[D];
    __shared__ float sh_red[T];
    __shared__ int   sh_ty[G1];

    // Register-cached attention weights for THIS warp's type (= warp id).
    float w1reg[D];
    {
        const float* w1 = tw1 + warp * (D * A);
        #pragma unroll
        for (int d = 0; d < D; ++d) w1reg[d] = w1[d * A + lane];
    }
    const float tw2v = tw2[warp * A + lane];

    const int b0 = blockIdx.x * G1;
    if (threadIdx.x < G1 && b0 + threadIdx.x < B)
        sh_ty[threadIdx.x] = types[b0 + threadIdx.x];
    __syncthreads();

    #pragma unroll 1
    for (int g = 0; g < G1; ++g) {
        const int b = b0 + g;
        if (b >= B) return;                // uniform across CTA

        // ---- neighbor gather + mean: warp t, lane d ----
        int nbv = 0;
        if (lane < S) nbv = neighbors[b * (T * S) + warp * S + lane];

        float acc = 0.0f;
        #pragma unroll
        for (int s = 0; s < S; ++s) {
            const int v = __shfl_sync(0xffffffffu, nbv, s);
            acc += __ldg(&nte[(size_t)v * (T * D) + warp * D + lane]);
        }
        sh_agg[warp][lane] = acc * (1.0f / (float)S);
        __syncthreads();

        const int ty = sh_ty[g];

        // ---- attention: the warp owning types[b]'s weights does it all ----
        if (warp == ty) {
            float score[T];
            #pragma unroll
            for (int t = 0; t < T; ++t) {
                float dot = 0.0f;
                const float4* ap = (const float4*)sh_agg[t];
                #pragma unroll
                for (int q = 0; q < D / 4; ++q) {
                    const float4 v4 = ap[q];       // LDS.128 broadcast
                    dot = fmaf(v4.x, w1reg[4 * q + 0], dot);
                    dot = fmaf(v4.y, w1reg[4 * q + 1], dot);
                    dot = fmaf(v4.z, w1reg[4 * q + 2], dot);
                    dot = fmaf(v4.w, w1reg[4 * q + 3], dot);
                }
                float u = tanhf(dot) * tw2v;
                #pragma unroll
                for (int off = 16; off > 0; off >>= 1)
                    u += __shfl_xor_sync(0xffffffffu, u, off);
                score[t] = u;
            }
            const float m  = fmaxf(fmaxf(score[0], score[1]),
                                   fmaxf(score[2], score[3]));
            const float e0 = __expf(score[0] - m), e1 = __expf(score[1] - m);
            const float e2 = __expf(score[2] - m), e3 = __expf(score[3] - m);
            const float inv = 1.0f / (e0 + e1 + e2 + e3);
            sh_natt[lane] = (e0 * sh_agg[0][lane] + e1 * sh_agg[1][lane] +
                             e2 * sh_agg[2][lane] + e3 * sh_agg[3][lane]) * inv;
        }
        __syncthreads();

        // ---- projection: thread handles output e = warp*32 + lane ----
        // tw slice for this b: 16KB read via L1 (tw total 64KB, L1-resident)
        const float* w = tw + (size_t)ty * (D * E) + warp * 32 + lane;
        float p = 0.0f;
        const float4* np = (const float4*)sh_natt;
        #pragma unroll
        for (int q = 0; q < D / 4; ++q) {
            const float4 n4 = np[q];               // LDS.128 broadcast
            p = fmaf(n4.x, __ldg(w + (4 * q + 0) * E), p);
            p = fmaf(n4.y, __ldg(w + (4 * q + 1) * E), p);
            p = fmaf(n4.z, __ldg(w + (4 * q + 2) * E), p);
            p = fmaf(n4.w, __ldg(w + (4 * q + 3) * E), p);
        }

        const int tgt = targets[b];                // broadcast load
        const float val = __ldg(&base_emb[(size_t)tgt * E + threadIdx.x]) + p;

        // ---- l2 normalize across the 128 outputs ----
        float ss = val * val;
        #pragma unroll
        for (int off = 16; off > 0; off >>= 1)
            ss += __shfl_xor_sync(0xffffffffu, ss, off);
        if (lane == 0) sh_red[warp] = ss;
        __syncthreads();
        const float tot = sh_red[0] + sh_red[1] + sh_red[2] + sh_red[3];
        const float r = rsqrtf(fmaxf(tot, 1e-12f));

        out[(size_t)b * E + threadIdx.x] = val * r;
        // no extra barrier needed: sh_agg/sh_natt writes of iter g+1 happen
        // after the gather barrier of iter g+1, which orders them after all
        // reads above.
    }
}

extern "C" void kernel_launch(void* const* d_in, const int* in_sizes, int n_in,
                              void* d_out, int out_size) {
    const int*   targets   = (const int*)  d_in[0];
    const int*   types     = (const int*)  d_in[1];
    const int*   neighbors = (const int*)  d_in[2];
    const float* base_emb  = (const float*)d_in[3];
    const float* nte       = (const float*)d_in[4];
    const float* tw        = (const float*)d_in[5];
    const float* tw1       = (const float*)d_in[6];
    const float* tw2       = (const float*)d_in[7];
    float* out = (float*)d_out;

    const int B = in_sizes[0];
    const int grid = (B + G1 - 1) / G1;
    gatne_fused<<<grid, 128>>>(targets, types, neighbors,
                               base_emb, nte, tw, tw1, tw2, out, B);
}

// round 5
// speedup vs baseline: 1.4100x; 1.4100x over previous
#include <cuda_runtime.h>
#include <cstddef>

// GATNE-T fully fused single kernel (R5).
// Inputs (metadata order):
//  0 targets   int32  [B]
//  1 types     int32  [B]
//  2 neighbors int32  [B,T,S]
//  3 base_node_embeddings float [V,E]
//  4 node_type_embeddings float [V,T,D]
//  5 trans_weights    float [T,D,E]
//  6 trans_weights_s1 float [T,D,A]
//  7 trans_weights_s2 float [T,A,1]
// Output: float [B,E]
//
// 128 threads = 4 warps per CTA, G1=4 batch elements per CTA (grid=2048).
// Per b:
//   gather:    warp t, lane d -> sh_agg[t][d]  (40 coalesced random 128B LDG)
//   attention: warp whose id == types[b] (register-cached W1/w2 for its type)
//   projection: warp w -> outputs [32w,32w+32); lane=(dgrp,eslot); float4
//               L1-hit weight loads, d-split + shfl butterfly reduction
//   l2 norm:   warp partials -> smem -> rsqrt, float4 store.

namespace {
constexpr int T = 4;
constexpr int S = 10;
constexpr int D = 32;
constexpr int E = 128;
constexpr int A = 32;
constexpr int G1 = 4;     // batch elements per CTA
}

__global__ __launch_bounds__(128) void gatne_fused(
    const int*   __restrict__ targets,
    const int*   __restrict__ types,
    const int*   __restrict__ neighbors,  // [B,T,S]
    const float* __restrict__ base_emb,   // [V,E]
    const float* __restrict__ nte,        // [V,T,D]
    const float* __restrict__ tw,         // [T,D,E]
    const float* __restrict__ tw1,        // [T,D,A]
    const float* __restrict__ tw2,        // [T,A]
    float*       __restrict__ out,        // [B,E]
    int B)
{
    const int tid   = threadIdx.x;
    const int warp  = tid >> 5;
    const int lane  = tid & 31;
    const int dgrp  = lane >> 3;   // 0..3 : d-range [8*dgrp, 8*dgrp+8)
    const int eslot = lane & 7;    // 0..7 : float4 slot within warp's 32 e's

    __shared__ float sh_agg[T][D];
    __shared__ float sh_natt[D];
    __shared__ float sh_red[T];
    __shared__ int   sh_nb[G1 * T * S];
    __shared__ int   sh_ty[G1];
    __shared__ int   sh_tgt[G1];

    // Register-cached attention weights for THIS warp's type (= warp id).
    float w1reg[D];
    {
        const float* w1 = tw1 + warp * (D * A);
        #pragma unroll
        for (int d = 0; d < D; ++d) w1reg[d] = w1[d * A + lane];
    }
    const float tw2v = tw2[warp * A + lane];

    const int b0 = blockIdx.x * G1;

    // Stage per-b metadata (coalesced) once per CTA.
    for (int i = tid; i < G1 * T * S; i += 128) {
        const int bb = b0 + i / (T * S);
        if (bb < B) sh_nb[i] = neighbors[(size_t)b0 * (T * S) + i];
    }
    if (tid < G1 && b0 + tid < B) {
        sh_ty[tid]  = types[b0 + tid];
        sh_tgt[tid] = targets[b0 + tid];
    }
    __syncthreads();

    #pragma unroll 1
    for (int g = 0; g < G1; ++g) {
        const int b = b0 + g;
        if (b >= B) return;                // uniform across CTA

        // ---- neighbor gather + mean: warp t, lane d ----
        int nbv = 0;
        if (lane < S) nbv = sh_nb[g * (T * S) + warp * S + lane];

        float acc = 0.0f;
        #pragma unroll
        for (int s = 0; s < S; ++s) {
            const int v = __shfl_sync(0xffffffffu, nbv, s);
            acc += __ldg(&nte[(size_t)v * (T * D) + warp * D + lane]);
        }
        sh_agg[warp][lane] = acc * (1.0f / (float)S);
        __syncthreads();                   // B1

        const int ty = sh_ty[g];

        // ---- attention: the warp owning types[b]'s weights does it all ----
        if (warp == ty) {
            float score[T];
            #pragma unroll
            for (int t = 0; t < T; ++t) {
                float dot = 0.0f;
                const float4* ap = (const float4*)sh_agg[t];
                #pragma unroll
                for (int q = 0; q < D / 4; ++q) {
                    const float4 v4 = ap[q];       // LDS.128 broadcast
                    dot = fmaf(v4.x, w1reg[4 * q + 0], dot);
                    dot = fmaf(v4.y, w1reg[4 * q + 1], dot);
                    dot = fmaf(v4.z, w1reg[4 * q + 2], dot);
                    dot = fmaf(v4.w, w1reg[4 * q + 3], dot);
                }
                float u = tanhf(dot) * tw2v;
                #pragma unroll
                for (int off = 16; off > 0; off >>= 1)
                    u += __shfl_xor_sync(0xffffffffu, u, off);
                score[t] = u;
            }
            const float m  = fmaxf(fmaxf(score[0], score[1]),
                                   fmaxf(score[2], score[3]));
            const float e0 = __expf(score[0] - m), e1 = __expf(score[1] - m);
            const float e2 = __expf(score[2] - m), e3 = __expf(score[3] - m);
            const float inv = 1.0f / (e0 + e1 + e2 + e3);
            sh_natt[lane] = (e0 * sh_agg[0][lane] + e1 * sh_agg[1][lane] +
                             e2 * sh_agg[2][lane] + e3 * sh_agg[3][lane]) * inv;
        }
        __syncthreads();                   // B2

        // ---- projection: warp w -> e in [32w, 32w+32), float4 + d-split ----
        const float nat = sh_natt[lane];   // lane = d, one LDS per warp
        const float* wbase = tw + (size_t)ty * (D * E) + warp * 32 + 4 * eslot;

        float4 a4 = make_float4(0.f, 0.f, 0.f, 0.f);
        #pragma unroll
        for (int i = 0; i < 8; ++i) {
            const int d = dgrp * 8 + i;
            const float nd = __shfl_sync(0xffffffffu, nat, d);
            const float4 w4 = __ldg((const float4*)(wbase + d * E)); // L1 hit
            a4.x = fmaf(nd, w4.x, a4.x);
            a4.y = fmaf(nd, w4.y, a4.y);
            a4.z = fmaf(nd, w4.z, a4.z);
            a4.w = fmaf(nd, w4.w, a4.w);
        }
        // butterfly reduce over dgrp (lanes l, l^8, l^16, l^24)
        #pragma unroll
        for (int off = 8; off <= 16; off <<= 1) {
            a4.x += __shfl_xor_sync(0xffffffffu, a4.x, off);
            a4.y += __shfl_xor_sync(0xffffffffu, a4.y, off);
            a4.z += __shfl_xor_sync(0xffffffffu, a4.z, off);
            a4.w += __shfl_xor_sync(0xffffffffu, a4.w, off);
        }

        const float4 bv = __ldg((const float4*)(
            base_emb + (size_t)sh_tgt[g] * E + warp * 32 + 4 * eslot));
        const float4 val = make_float4(a4.x + bv.x, a4.y + bv.y,
                                       a4.z + bv.z, a4.w + bv.w);

        // ---- l2 norm: each value replicated 4x across dgrp -> scale 0.25 ----
        float ss = val.x * val.x + val.y * val.y + val.z * val.z + val.w * val.w;
        #pragma unroll
        for (int off = 16; off > 0; off >>= 1)
            ss += __shfl_xor_sync(0xffffffffu, ss, off);
        if (lane == 0) sh_red[warp] = ss * 0.25f;
        __syncthreads();                   // B3
        const float tot = sh_red[0] + sh_red[1] + sh_red[2] + sh_red[3];
        const float r = rsqrtf(fmaxf(tot, 1e-12f));

        if (dgrp == 0) {
            const float4 o = make_float4(val.x * r, val.y * r,
                                         val.z * r, val.w * r);
            *(float4*)(out + (size_t)b * E + warp * 32 + 4 * eslot) = o;
        }
    }
}

extern "C" void kernel_launch(void* const* d_in, const int* in_sizes, int n_in,
                              void* d_out, int out_size) {
    const int*   targets   = (const int*)  d_in[0];
    const int*   types     = (const int*)  d_in[1];
    const int*   neighbors = (const int*)  d_in[2];
    const float* base_emb  = (const float*)d_in[3];
    const float* nte       = (const float*)d_in[4];
    const float* tw        = (const float*)d_in[5];
    const float* tw1       = (const float*)d_in[6];
    const float* tw2       = (const float*)d_in[7];
    float* out = (float*)d_out;

    const int B = in_sizes[0];
    const int grid = (B + G1 - 1) / G1;
    gatne_fused<<<grid, 128>>>(targets, types, neighbors,
                               base_emb, nte, tw, tw1, tw2, out, B);
}

// round 6
// speedup vs baseline: 1.6855x; 1.1954x over previous
#include <cuda_runtime.h>
#include <cstddef>

// GATNE-T fused, warp-per-batch-element, zero CTA barriers (R6).
// Inputs (metadata order):
//  0 targets   int32  [B]
//  1 types     int32  [B]
//  2 neighbors int32  [B,T,S]
//  3 base_node_embeddings float [V,E]
//  4 node_type_embeddings float [V,T,D]
//  5 trans_weights    float [T,D,E]
//  6 trans_weights_s1 float [T,D,A]
//  7 trans_weights_s2 float [T,A,1]
// Output: float [B,E]

namespace {
constexpr int T = 4;
constexpr int S = 10;
constexpr int D = 32;
constexpr int E = 128;
constexpr int A = 32;
constexpr int NW = 8;          // warps per CTA
}

__global__ __launch_bounds__(32 * NW) void gatne_warp(
    const int*   __restrict__ targets,
    const int*   __restrict__ types,
    const int*   __restrict__ neighbors,  // [B,T,S]
    const float* __restrict__ base_emb,   // [V,E]
    const float* __restrict__ nte,        // [V,T,D]
    const float* __restrict__ tw,         // [T,D,E]
    const float* __restrict__ tw1,        // [T,D,A]
    const float* __restrict__ tw2,        // [T,A]
    float*       __restrict__ out,        // [B,E]
    int B)
{
    const int wid  = threadIdx.x >> 5;
    const int lane = threadIdx.x & 31;

    // per-warp scratch for broadcasts (no cross-warp sharing, no barriers)
    __shared__ float sh_agg[NW][T][D];
    __shared__ float sh_nat[NW][D];

    const int b = blockIdx.x * NW + wid;
    if (b >= B) return;

    const int ty  = types[b];      // broadcast LDG
    const int tgt = targets[b];    // broadcast LDG

    // ---- neighbor indices: 2 coalesced loads for 40 ints ----
    const int* nbp = neighbors + (size_t)b * (T * S);
    const int nbv0 = nbp[lane];
    const int nbv1 = (lane < T * S - 32) ? nbp[32 + lane] : 0;

    // ---- gather + mean: 40 independent coalesced 128B loads, lane = d ----
    float acc[T];
    #pragma unroll
    for (int t = 0; t < T; ++t) acc[t] = 0.0f;

    #pragma unroll
    for (int t = 0; t < T; ++t) {
        #pragma unroll
        for (int s = 0; s < S; ++s) {
            const int flat = t * S + s;
            const int v = (flat < 32)
                ? __shfl_sync(0xffffffffu, nbv0, flat)
                : __shfl_sync(0xffffffffu, nbv1, flat - 32);
            acc[t] += __ldg(&nte[(size_t)v * (T * D) + t * D + lane]);
        }
    }
    #pragma unroll
    for (int t = 0; t < T; ++t) {
        acc[t] *= (1.0f / (float)S);       // agg[t][lane]
        sh_agg[wid][t][lane] = acc[t];
    }

    // ---- attention weights for this b's type (L1-resident, 16KB table) ----
    float w1col[D];                        // W1[ty][d][lane], lane = a
    {
        const float* w1 = tw1 + (size_t)ty * (D * A);
        #pragma unroll
        for (int d = 0; d < D; ++d) w1col[d] = __ldg(&w1[d * A + lane]);
    }
    const float tw2v = __ldg(&tw2[ty * A + lane]);

    __syncwarp();

    // ---- scores: u[t][a] = tanh(agg[t] . W1col[:,a]);  sc[t] = u . w2 ----
    float score[T];
    #pragma unroll
    for (int t = 0; t < T; ++t) {
        float dot = 0.0f;
        const float4* ap = (const float4*)sh_agg[wid][t];
        #pragma unroll
        for (int q = 0; q < D / 4; ++q) {
            const float4 v4 = ap[q];       // broadcast LDS.128
            dot = fmaf(v4.x, w1col[4 * q + 0], dot);
            dot = fmaf(v4.y, w1col[4 * q + 1], dot);
            dot = fmaf(v4.z, w1col[4 * q + 2], dot);
            dot = fmaf(v4.w, w1col[4 * q + 3], dot);
        }
        float u = tanhf(dot) * tw2v;
        #pragma unroll
        for (int off = 16; off > 0; off >>= 1)
            u += __shfl_xor_sync(0xffffffffu, u, off);
        score[t] = u;
    }

    // ---- softmax over T=4 + attended embedding (lane = d) ----
    const float m  = fmaxf(fmaxf(score[0], score[1]),
                           fmaxf(score[2], score[3]));
    const float e0 = __expf(score[0] - m), e1 = __expf(score[1] - m);
    const float e2 = __expf(score[2] - m), e3 = __expf(score[3] - m);
    const float inv = 1.0f / (e0 + e1 + e2 + e3);
    const float natt = (e0 * acc[0] + e1 * acc[1] +
                        e2 * acc[2] + e3 * acc[3]) * inv;
    sh_nat[wid][lane] = natt;
    __syncwarp();

    // ---- projection: lane owns e in [4*lane, 4*lane+4); warp covers E ----
    const float* wbase = tw + (size_t)ty * (D * E) + 4 * lane;
    float4 a4 = make_float4(0.f, 0.f, 0.f, 0.f);
    const float4* np = (const float4*)sh_nat[wid];
    #pragma unroll
    for (int q = 0; q < D / 4; ++q) {
        const float4 n4 = np[q];           // broadcast LDS.128
        #pragma unroll
        for (int j = 0; j < 4; ++j) {
            const int d = 4 * q + j;
            const float nd = (j == 0) ? n4.x : (j == 1) ? n4.y
                           : (j == 2) ? n4.z : n4.w;
            const float4 w4 = __ldg((const float4*)(wbase + d * E)); // L1 hit
            a4.x = fmaf(nd, w4.x, a4.x);
            a4.y = fmaf(nd, w4.y, a4.y);
            a4.z = fmaf(nd, w4.z, a4.z);
            a4.w = fmaf(nd, w4.w, a4.w);
        }
    }

    const float4 bv = __ldg((const float4*)(base_emb + (size_t)tgt * E) + lane);
    const float4 val = make_float4(a4.x + bv.x, a4.y + bv.y,
                                   a4.z + bv.z, a4.w + bv.w);

    // ---- l2 norm: warp butterfly = exact sum over all 128 outputs ----
    float ss = val.x * val.x + val.y * val.y + val.z * val.z + val.w * val.w;
    #pragma unroll
    for (int off = 16; off > 0; off >>= 1)
        ss += __shfl_xor_sync(0xffffffffu, ss, off);
    const float r = rsqrtf(fmaxf(ss, 1e-12f));

    const float4 o = make_float4(val.x * r, val.y * r, val.z * r, val.w * r);
    ((float4*)(out + (size_t)b * E))[lane] = o;
}

extern "C" void kernel_launch(void* const* d_in, const int* in_sizes, int n_in,
                              void* d_out, int out_size) {
    const int*   targets   = (const int*)  d_in[0];
    const int*   types     = (const int*)  d_in[1];
    const int*   neighbors = (const int*)  d_in[2];
    const float* base_emb  = (const float*)d_in[3];
    const float* nte       = (const float*)d_in[4];
    const float* tw        = (const float*)d_in[5];
    const float* tw1       = (const float*)d_in[6];
    const float* tw2       = (const float*)d_in[7];
    float* out = (float*)d_out;

    const int B = in_sizes[0];
    const int grid = (B + NW - 1) / NW;
    gatne_warp<<<grid, 32 * NW>>>(targets, types, neighbors,
                                  base_emb, nte, tw, tw1, tw2, out, B);
}